// round 5
// baseline (speedup 1.0000x reference)
#include <cuda_runtime.h>

#define HH 256
#define WW 256
#define BB 2
#define CC 4
#define GRID (BB*64)         // 128 blocks: 4 rows each
#define NTOT (BB*CC*HH*WW)   // 524288
#define FPS 4096.0f
#define INV_FPS (1.0f/4096.0f)

// Per-block integer partials (written fresh every run)
__device__ int g_pA[GRID];
__device__ int g_pS[GRID][CC];
__device__ int g_pM[GRID][CC];
__device__ unsigned int g_cnt = 0;

__device__ __forceinline__ int labAt(const int* __restrict__ y, int shift,
                                     int b, int idx) {
    return y[((b << 16) + idx) << shift];
}

__global__ void __launch_bounds__(256) rw_fused(const int* __restrict__ y,
                                                const float* __restrict__ x,
                                                float* __restrict__ out) {
    __shared__ int slab[6][WW];          // label rows hg-1 .. hg+4
    __shared__ int s_shift, s_last;
    __shared__ int sA, sS[CC], sM[CC];
    __shared__ int fA, fS[2*CC], fM[2*CC];

    const int bid  = blockIdx.x;
    const int b    = bid >> 6;
    const int hg   = (bid & 63) << 2;    // first of 4 rows
    const int t    = threadIdx.x;
    const int lane = t & 31;
    const int rsel = t >> 6;             // 0..3
    const int wq   = (t & 63) << 2;      // 4-pixel strip start
    const int rr   = hg + rsel;
    const int jr   = rsel + 1;           // local smem row

    // ---- x loads first: 4 independent float4 (deep MLP, overlaps sniff) ----
    float4 xr[CC];
    #pragma unroll
    for (int c = 0; c < CC; c++)
        xr[c] = *(const float4*)&x[((b * CC + c) << 16) + (rr << 8) + wq];

    // ---- dtype sniff (warp 0): int64 LE => odd words all zero ----
    if (t < 32) {
        int odd  = y[2 * t + 1];
        int is64 = __all_sync(0xffffffffu, odd == 0);
        if (t == 0) s_shift = is64;
    }
    if (t == 64) sA = 0;
    if (t >= 96 && t < 96 + CC) { sS[t - 96] = 0; sM[t - 96] = 0; }
    if (t >= 128 && t < 128 + 2*CC) { fS[t - 128] = 0; fM[t - 128] = 0; }
    if (t == 160) fA = 0;
    __syncthreads();
    const int shift = s_shift;

    // ---- stage 6 label rows: thread t = column t, 6 independent loads ----
    #pragma unroll
    for (int j = 0; j < 6; j++) {
        int row = hg - 1 + j;
        if (row >= 0 && row < HH)
            slab[j][t] = labAt(y, shift, b, (row << 8) + t);
    }
    __syncthreads();

    // ---- 4 pixels per thread ----
    float A = 0.0f, S4[CC] = {0, 0, 0, 0};
    int   M4[CC] = {0, 0, 0, 0};

    #pragma unroll
    for (int p = 0; p < 4; p++) {
        const int w = wq + p;
        const int L = slab[jr][w];

        // d^2 to nearest differing label (integer-exact)
        int best;
        bool ax = (w > 0      && slab[jr][w-1]   != L) ||
                  (w < WW-1   && slab[jr][w+1]   != L) ||
                  (rr > 0     && slab[jr-1][w]   != L) ||
                  (rr < HH-1  && slab[jr+1][w]   != L);
        if (ax) {
            best = 1;
        } else {
            bool dg = false;
            if (rr > 0) {
                if (w > 0    && slab[jr-1][w-1] != L) dg = true;
                if (w < WW-1 && slab[jr-1][w+1] != L) dg = true;
            }
            if (rr < HH-1) {
                if (w > 0    && slab[jr+1][w-1] != L) dg = true;
                if (w < WW-1 && slab[jr+1][w+1] != L) dg = true;
            }
            best = dg ? 2 : 0x7fffffff;
            // Rare general rings (3x3 uniform patch: p ~ 4^-8)
            for (int R = 2; R < 512 && R * R < best; R++) {
                int hm = rr - R, hp = rr + R, wm = w - R, wpp = w + R;
                int wlo = wm < 0 ? 0 : wm, whi = wpp > WW-1 ? WW-1 : wpp;
                if (hm >= 0)
                    for (int ww = wlo; ww <= whi; ww++)
                        if (labAt(y, shift, b, hm * WW + ww) != L) {
                            int dw = ww - w, d2 = R*R + dw*dw;
                            if (d2 < best) best = d2;
                        }
                if (hp <= HH-1)
                    for (int ww = wlo; ww <= whi; ww++)
                        if (labAt(y, shift, b, hp * WW + ww) != L) {
                            int dw = ww - w, d2 = R*R + dw*dw;
                            if (d2 < best) best = d2;
                        }
                int hlo = hm + 1 < 0 ? 0 : hm + 1;
                int hhi = hp - 1 > HH-1 ? HH-1 : hp - 1;
                if (wm >= 0)
                    for (int hh = hlo; hh <= hhi; hh++)
                        if (labAt(y, shift, b, hh * WW + wm) != L) {
                            int dh = hh - rr, d2 = R*R + dh*dh;
                            if (d2 < best) best = d2;
                        }
                if (wpp <= WW-1)
                    for (int hh = hlo; hh <= hhi; hh++)
                        if (labAt(y, shift, b, hh * WW + wpp) != L) {
                            int dh = hh - rr, d2 = R*R + dh*dh;
                            if (d2 < best) best = d2;
                        }
            }
        }

        // softmax p_L: exps relative to class 0 (3 MUFU + 1 RCP)
        float v0 = ((const float*)&xr[0])[p];
        float e1 = __expf(((const float*)&xr[1])[p] - v0);
        float e2 = __expf(((const float*)&xr[2])[p] - v0);
        float e3 = __expf(((const float*)&xr[3])[p] - v0);
        float eL = (L == 0) ? 1.0f : (L == 1) ? e1 : (L == 2) ? e2 : e3;
        float pL = eL * __frcp_rn(1.0f + e1 + e2 + e3);

        float sd = (best == 1) ? 1.0f
                 : (best == 2) ? 1.41421356237f
                 : sqrtf((float)best);

        A += 1.0f - pL;
        float psd = pL * sd;
        #pragma unroll
        for (int c = 0; c < CC; c++) {
            S4[c] += (L == c) ? psd : 0.0f;
            M4[c]  = max(M4[c], (L == c) ? best : 0);
        }
    }

    // ---- fixed-point block reduction ----
    int ai = __float2int_rn(A * FPS);
    ai = __reduce_add_sync(0xffffffffu, ai);
    int si[CC];
    #pragma unroll
    for (int c = 0; c < CC; c++) {
        si[c]  = __reduce_add_sync(0xffffffffu, __float2int_rn(S4[c] * FPS));
        M4[c]  = __reduce_max_sync(0xffffffffu, M4[c]);
    }
    if (lane == 0) {
        atomicAdd(&sA, ai);
        #pragma unroll
        for (int c = 0; c < CC; c++) {
            atomicAdd(&sS[c], si[c]);
            atomicMax(&sM[c], M4[c]);
        }
    }
    __syncthreads();

    // ---- publish + last-block detection ----
    if (t == 0) {
        g_pA[bid] = sA;
        #pragma unroll
        for (int c = 0; c < CC; c++) { g_pS[bid][c] = sS[c]; g_pM[bid][c] = sM[c]; }
        __threadfence();
        unsigned int old = atomicAdd(&g_cnt, 1u);
        s_last = (old == GRID - 1);
    }
    __syncthreads();
    if (!s_last) return;

    // ---- tail: 128 partials, 4 warps, uniform b per warp ----
    if (t < GRID) {
        const int bb = t >> 6;
        int tA = __ldcg(&g_pA[t]);
        int tS[CC], tM[CC];
        #pragma unroll
        for (int c = 0; c < CC; c++) {
            tS[c] = __ldcg(&g_pS[t][c]);
            tM[c] = __ldcg(&g_pM[t][c]);
        }
        tA = __reduce_add_sync(0xffffffffu, tA);
        #pragma unroll
        for (int c = 0; c < CC; c++) {
            tS[c] = __reduce_add_sync(0xffffffffu, tS[c]);
            tM[c] = __reduce_max_sync(0xffffffffu, tM[c]);
        }
        if (lane == 0) {
            atomicAdd(&fA, tA);
            #pragma unroll
            for (int c = 0; c < CC; c++) {
                atomicAdd(&fS[bb * CC + c], tS[c]);
                atomicMax(&fM[bb * CC + c], tM[c]);
            }
        }
    }
    __syncthreads();
    if (t == 0) {
        float res = (float)fA * INV_FPS;
        #pragma unroll
        for (int k = 0; k < 2*CC; k++)
            res -= ((float)fS[k] * INV_FPS) / (sqrtf((float)fM[k]) + 1e-15f);
        out[0] = res * (1.0f / (float)NTOT);
        __threadfence();
        g_cnt = 0;                       // reset for graph replay
    }
}

// ---------------------------------------------------------------------------
extern "C" void kernel_launch(void* const* d_in, const int* in_sizes, int n_in,
                              void* d_out, int out_size) {
    const float* x;
    const void*  y;
    if (in_sizes[0] == NTOT) { x = (const float*)d_in[0]; y = d_in[1]; }
    else                     { x = (const float*)d_in[1]; y = d_in[0]; }

    rw_fused<<<GRID, 256>>>((const int*)y, x, (float*)d_out);
}

// round 6
// speedup vs baseline: 1.0269x; 1.0269x over previous
#include <cuda_runtime.h>

#define HH 256
#define WW 256
#define BB 2
#define CC 4
#define NROWS (BB*HH)        // 512 blocks, one per (b,h) row
#define NTOT (BB*CC*HH*WW)   // 524288
#define FPS 4096.0f
#define INV_FPS (1.0f/4096.0f)

// Global integer accumulators (zero-init; last block resets after each run)
__device__ int gA = 0;
__device__ int gS[2*CC] = {0,0,0,0,0,0,0,0};
__device__ int gM[2*CC] = {0,0,0,0,0,0,0,0};
__device__ unsigned int g_cnt = 0;

__device__ __forceinline__ int labAt(const int* __restrict__ y, int shift,
                                     int b, int idx) {
    return y[((b << 16) + idx) << shift];
}

__global__ void __launch_bounds__(256) rw_fused(const int* __restrict__ y,
                                                const float* __restrict__ x,
                                                float* __restrict__ out) {
    __shared__ int sl[3][WW];            // label rows h-1, h, h+1
    __shared__ int sA, sS[CC], sM[CC];
    __shared__ int s_last;

    const int r    = blockIdx.x;         // b*256 + h
    const int b    = r >> 8;
    const int h    = r & 255;
    const int w    = threadIdx.x;
    const int lane = w & 31;
    const int hw   = (h << 8) + w;

    // ---- round 1: x loads + per-warp dtype sniff (same memory round) ----
    float xv[CC];
    #pragma unroll
    for (int c = 0; c < CC; c++)
        xv[c] = __ldg(&x[((b * CC + c) << 16) + hw]);

    // words 1,3,..,63 are in-bounds under either dtype; int64 LE => all zero
    int odd   = __ldg(&y[2 * lane + 1]);
    int is64  = __all_sync(0xffffffffu, odd == 0);
    const int shift = is64 ? 1 : 0;

    if (w < CC)   { sS[w] = 0; sM[w] = 0; }
    if (w == 32)  sA = 0;

    // ---- round 2: stage 3 label rows ----
    #pragma unroll
    for (int k = 0; k < 3; k++) {
        int hh = h - 1 + k;
        if (hh >= 0 && hh < HH)
            sl[k][w] = labAt(y, shift, b, (hh << 8) + w);
    }
    __syncthreads();

    const int L = sl[1][w];

    // ---- d^2 to nearest differing label (integer-exact ring search) ----
    int best;
    bool ax = (w > 0      && sl[1][w-1] != L) ||
              (w < WW-1   && sl[1][w+1] != L) ||
              (h > 0      && sl[0][w]   != L) ||
              (h < HH-1   && sl[2][w]   != L);
    if (ax) {
        best = 1;
    } else {
        bool dg = false;
        if (h > 0) {
            if (w > 0    && sl[0][w-1] != L) dg = true;
            if (w < WW-1 && sl[0][w+1] != L) dg = true;
        }
        if (h < HH-1) {
            if (w > 0    && sl[2][w-1] != L) dg = true;
            if (w < WW-1 && sl[2][w+1] != L) dg = true;
        }
        best = dg ? 2 : 0x7fffffff;
        // Rare general rings (needs a 3x3 uniform patch: p ~ 4^-8)
        for (int R = 2; R < 512 && R * R < best; R++) {
            int hm = h - R, hp = h + R, wm = w - R, wp = w + R;
            int wlo = wm < 0 ? 0 : wm, whi = wp > WW-1 ? WW-1 : wp;
            if (hm >= 0)
                for (int ww = wlo; ww <= whi; ww++)
                    if (labAt(y, shift, b, hm * WW + ww) != L) {
                        int dw = ww - w, d2 = R*R + dw*dw;
                        if (d2 < best) best = d2;
                    }
            if (hp <= HH-1)
                for (int ww = wlo; ww <= whi; ww++)
                    if (labAt(y, shift, b, hp * WW + ww) != L) {
                        int dw = ww - w, d2 = R*R + dw*dw;
                        if (d2 < best) best = d2;
                    }
            int hlo = hm + 1 < 0 ? 0 : hm + 1;
            int hhi = hp - 1 > HH-1 ? HH-1 : hp - 1;
            if (wm >= 0)
                for (int hh = hlo; hh <= hhi; hh++)
                    if (labAt(y, shift, b, hh * WW + wm) != L) {
                        int dh = hh - h, d2 = R*R + dh*dh;
                        if (d2 < best) best = d2;
                    }
            if (wp <= WW-1)
                for (int hh = hlo; hh <= hhi; hh++)
                    if (labAt(y, shift, b, hh * WW + wp) != L) {
                        int dh = hh - h, d2 = R*R + dh*dh;
                        if (d2 < best) best = d2;
                    }
        }
    }

    // ---- softmax p_L: exps relative to class 0 (3 MUFU + 1 RCP) ----
    float e1 = __expf(xv[1] - xv[0]);
    float e2 = __expf(xv[2] - xv[0]);
    float e3 = __expf(xv[3] - xv[0]);
    float eL = (L == 0) ? 1.0f : (L == 1) ? e1 : (L == 2) ? e2 : e3;
    float pL = eL * __frcp_rn(1.0f + e1 + e2 + e3);

    float sd = (best == 1) ? 1.0f
             : (best == 2) ? 1.41421356237f
             : sqrtf((float)best);

    // ---- fixed-point warp reduction (REDUX) ----
    int ai = __reduce_add_sync(0xffffffffu, __float2int_rn((1.0f - pL) * FPS));
    int si = __float2int_rn(pL * sd * FPS);
    int wS[CC], wM[CC];
    #pragma unroll
    for (int c = 0; c < CC; c++) {
        wS[c] = __reduce_add_sync(0xffffffffu, (L == c) ? si : 0);
        wM[c] = __reduce_max_sync(0xffffffffu, (L == c) ? best : 0);
    }
    if (lane == 0) {
        atomicAdd(&sA, ai);
        #pragma unroll
        for (int c = 0; c < CC; c++) {
            atomicAdd(&sS[c], wS[c]);
            atomicMax(&sM[c], wM[c]);
        }
    }
    __syncthreads();

    // ---- commit block partials straight to global accumulators ----
    if (w == 0)            atomicAdd(&gA, sA);
    else if (w < 1 + CC)   atomicAdd(&gS[b * CC + (w - 1)], sS[w - 1]);
    else if (w < 1 + 2*CC) atomicMax(&gM[b * CC + (w - 1 - CC)], sM[w - 1 - CC]);

    __threadfence();
    if (w == 0) {
        unsigned int old = atomicAdd(&g_cnt, 1u);
        s_last = (old == NROWS - 1);
    }
    __syncthreads();
    if (!s_last) return;

    // ---- last block: 17-value finalize + reset for graph replay ----
    if (w == 0) {
        float res = (float)__ldcg(&gA) * INV_FPS;
        #pragma unroll
        for (int k = 0; k < 2*CC; k++) {
            float Sk = (float)__ldcg(&gS[k]) * INV_FPS;
            float Mk = (float)__ldcg(&gM[k]);
            res -= Sk / (sqrtf(Mk) + 1e-15f);
        }
        out[0] = res * (1.0f / (float)NTOT);
        // reset accumulators for the next replay
        gA = 0;
        #pragma unroll
        for (int k = 0; k < 2*CC; k++) { gS[k] = 0; gM[k] = 0; }
        __threadfence();
        g_cnt = 0;
    }
}

// ---------------------------------------------------------------------------
extern "C" void kernel_launch(void* const* d_in, const int* in_sizes, int n_in,
                              void* d_out, int out_size) {
    const float* x;
    const void*  y;
    if (in_sizes[0] == NTOT) { x = (const float*)d_in[0]; y = d_in[1]; }
    else                     { x = (const float*)d_in[1]; y = d_in[0]; }

    rw_fused<<<NROWS, 256>>>((const int*)y, x, (float*)d_out);
}